// round 1
// baseline (speedup 1.0000x reference)
#include <cuda_runtime.h>
#include <cuda_bf16.h>
#include <math.h>

#define A_   128
#define D_   128
#define DM1  127
#define MAXB 64

// T_exp (softmax of u_log_transition rows), stored bf16, packed 4 per uint2.
__device__ uint2 g_T[(size_t)DM1 * A_ * A_ / 4];
__device__ float g_logpa1[A_];
__device__ float g_E[(size_t)MAXB * D_ * A_];

// ---------------------------------------------------------------------------
// Kernel A: row softmax of u_log_transition -> g_T (bf16 probabilities).
// One warp per row (128 elems, 4 per lane). grid = ceil(16256/8), block = 256.
// ---------------------------------------------------------------------------
__global__ void k_softmaxT(const float* __restrict__ u) {
    int w = threadIdx.x >> 5, lane = threadIdx.x & 31;
    int row = blockIdx.x * 8 + w;
    if (row >= DM1 * A_) return;
    float4 v4 = reinterpret_cast<const float4*>(u)[(size_t)row * 32 + lane];
    float m = fmaxf(fmaxf(v4.x, v4.y), fmaxf(v4.z, v4.w));
    #pragma unroll
    for (int o = 16; o > 0; o >>= 1) m = fmaxf(m, __shfl_xor_sync(0xffffffffu, m, o));
    float e0 = __expf(v4.x - m), e1 = __expf(v4.y - m);
    float e2 = __expf(v4.z - m), e3 = __expf(v4.w - m);
    float s = e0 + e1 + e2 + e3;
    #pragma unroll
    for (int o = 16; o > 0; o >>= 1) s += __shfl_xor_sync(0xffffffffu, s, o);
    float inv = 1.0f / s;
    __nv_bfloat162 p0 = __floats2bfloat162_rn(e0 * inv, e1 * inv);
    __nv_bfloat162 p1 = __floats2bfloat162_rn(e2 * inv, e3 * inv);
    uint2 ov;
    ov.x = *reinterpret_cast<unsigned int*>(&p0);
    ov.y = *reinterpret_cast<unsigned int*>(&p1);
    g_T[(size_t)row * 32 + lane] = ov;
}

// ---------------------------------------------------------------------------
// Kernel B: emission probabilities E[b,d,j] = exp(x*l - softplus(l)).
// One warp per (b,d) row. grid = ceil(B*D/8), block = 256.
// ---------------------------------------------------------------------------
__global__ void k_emis(const float* __restrict__ x, const float* __restrict__ lpx, int nrows) {
    int w = threadIdx.x >> 5, lane = threadIdx.x & 31;
    int row = blockIdx.x * 8 + w;           // row = b*D + d
    if (row >= nrows) return;
    int d = row & (D_ - 1);
    float xv = x[row];
    float4 l4 = reinterpret_cast<const float4*>(lpx)[(size_t)d * 32 + lane];
    float4 e4;
    {
        float l = l4.x; float sp = fmaxf(l, 0.f) + log1pf(__expf(-fabsf(l)));
        e4.x = __expf(xv * l - sp);
    }
    {
        float l = l4.y; float sp = fmaxf(l, 0.f) + log1pf(__expf(-fabsf(l)));
        e4.y = __expf(xv * l - sp);
    }
    {
        float l = l4.z; float sp = fmaxf(l, 0.f) + log1pf(__expf(-fabsf(l)));
        e4.z = __expf(xv * l - sp);
    }
    {
        float l = l4.w; float sp = fmaxf(l, 0.f) + log1pf(__expf(-fabsf(l)));
        e4.w = __expf(xv * l - sp);
    }
    reinterpret_cast<float4*>(g_E)[(size_t)row * 32 + lane] = e4;
}

// ---------------------------------------------------------------------------
// Kernel C: log_p_a1 = log_softmax(u_log_p_a1). 1 block, 128 threads.
// Also writes the second output tensor.
// ---------------------------------------------------------------------------
__global__ void k_logpa1(const float* __restrict__ u, float* __restrict__ out,
                         int base, int out_size) {
    __shared__ float sred[4];
    int t = threadIdx.x, lane = t & 31, w = t >> 5;
    float v = u[t];
    float m = v;
    #pragma unroll
    for (int o = 16; o > 0; o >>= 1) m = fmaxf(m, __shfl_xor_sync(0xffffffffu, m, o));
    if (lane == 0) sred[w] = m;
    __syncthreads();
    m = fmaxf(fmaxf(sred[0], sred[1]), fmaxf(sred[2], sred[3]));
    __syncthreads();
    float e = __expf(v - m);
    float s = e;
    #pragma unroll
    for (int o = 16; o > 0; o >>= 1) s += __shfl_xor_sync(0xffffffffu, s, o);
    if (lane == 0) sred[w] = s;
    __syncthreads();
    s = sred[0] + sred[1] + sred[2] + sred[3];
    float lp = v - m - logf(s);
    g_logpa1[t] = lp;
    int idx = base + t;
    if (idx < out_size) out[idx] = lp;
}

// ---------------------------------------------------------------------------
// Kernel D: main forward recurrence. grid = B, block = 256 (8 warps).
// Warp w owns k in [16w, 16w+16); lane owns j-quad 4*lane..4*lane+3.
// v kept in shared, rescaled by running max each step (scale folded into the
// next step's emission multiply; log-scale accumulated in s_acc).
// ---------------------------------------------------------------------------
__global__ void __launch_bounds__(256) k_forward(float* __restrict__ out, int out_size) {
    const int b = blockIdx.x;
    const int t = threadIdx.x;
    const int w = t >> 5, lane = t & 31;

    __shared__ float v_sh[A_];
    __shared__ float part[8][A_];
    __shared__ float s_red[8];
    __shared__ float s_inv, s_acc, s_res;

    const float* Eb = g_E + (size_t)b * D_ * A_;

    // ---- init (d = 0): v0[j] = E[b,0,j] * exp(log_p_a1[j]) ----
    if (t < A_) {
        float val = Eb[t] * __expf(g_logpa1[t]);
        v_sh[t] = val;
        float m = val;
        #pragma unroll
        for (int o = 16; o > 0; o >>= 1) m = fmaxf(m, __shfl_xor_sync(0xffffffffu, m, o));
        if (lane == 0) s_red[w] = m;
    }
    __syncthreads();
    if (t == 0) {
        float m = fmaxf(fmaxf(s_red[0], s_red[1]), fmaxf(s_red[2], s_red[3]));
        s_inv = 1.0f / m;
        s_acc = logf(m);
    }
    __syncthreads();

    const int kb = w * 16;

    for (int d = 1; d < D_; ++d) {
        // prefetch emission for this step (consumed after the barrier)
        float e_pref = 0.f;
        if (t < A_) e_pref = __ldg(Eb + d * A_ + t);

        // ---- k-loop: acc[j-quad] += v[k] * T[d-1][k][j] ----
        const uint2* Tq = g_T + ((size_t)(d - 1) * A_ + kb) * 32 + lane;
        float ax = 0.f, ay = 0.f, az = 0.f, aw = 0.f;
        #pragma unroll
        for (int kk = 0; kk < 16; ++kk) {
            float vk = v_sh[kb + kk];
            uint2 raw = Tq[kk * 32];
            float fx = __uint_as_float(raw.x << 16);
            float fy = __uint_as_float(raw.x & 0xffff0000u);
            float fz = __uint_as_float(raw.y << 16);
            float fw = __uint_as_float(raw.y & 0xffff0000u);
            ax = fmaf(vk, fx, ax);
            ay = fmaf(vk, fy, ay);
            az = fmaf(vk, fz, az);
            aw = fmaf(vk, fw, aw);
        }
        *reinterpret_cast<float4*>(&part[w][4 * lane]) = make_float4(ax, ay, az, aw);
        __syncthreads();

        // ---- combine partial sums, apply emission + pending rescale ----
        if (t < A_) {
            float s = part[0][t] + part[1][t] + part[2][t] + part[3][t]
                    + part[4][t] + part[5][t] + part[6][t] + part[7][t];
            float wv = s * (e_pref * s_inv);
            v_sh[t] = wv;
            float m = wv;
            #pragma unroll
            for (int o = 16; o > 0; o >>= 1) m = fmaxf(m, __shfl_xor_sync(0xffffffffu, m, o));
            if (lane == 0) s_red[w] = m;
        }
        __syncthreads();
        if (t == 0) {
            float m = fmaxf(fmaxf(s_red[0], s_red[1]), fmaxf(s_red[2], s_red[3]));
            s_inv = 1.0f / m;
            s_acc += logf(m);
        }
        // ordering for s_inv/s_acc provided by next iteration's first barrier
    }

    // ---- final: log_px[b] = s_acc + log(sum_j v[j] * s_inv) ----
    if (t < A_) {
        float sv = v_sh[t];
        #pragma unroll
        for (int o = 16; o > 0; o >>= 1) sv += __shfl_xor_sync(0xffffffffu, sv, o);
        if (lane == 0) s_red[w] = sv;
    }
    __syncthreads();
    if (t == 0) {
        float total = s_red[0] + s_red[1] + s_red[2] + s_red[3];
        s_res = s_acc + logf(total * s_inv);
    }
    __syncthreads();
    if (t < A_) {
        int idx = b * A_ + t;
        if (idx < out_size) out[idx] = s_res;
    }
}

// ---------------------------------------------------------------------------
extern "C" void kernel_launch(void* const* d_in, const int* in_sizes, int n_in,
                              void* d_out, int out_size) {
    const float* x     = (const float*)d_in[0];   // [B, D]
    const float* u_pa1 = (const float*)d_in[1];   // [1,1,1,A]
    const float* u_T   = (const float*)d_in[2];   // [D-1, A, A]
    const float* lpx   = (const float*)d_in[3];   // [1, D, 1, A]
    float* out = (float*)d_out;

    int B = in_sizes[0] / D_;
    if (B > MAXB) B = MAXB;

    // preprocessing
    k_softmaxT<<<(DM1 * A_ + 7) / 8, 256>>>(u_T);
    k_emis<<<(B * D_ + 7) / 8, 256>>>(x, lpx, B * D_);
    k_logpa1<<<1, 128>>>(u_pa1, out, B * A_, out_size);

    // main recurrence
    k_forward<<<B, 256>>>(out, out_size);
}

// round 2
// speedup vs baseline: 2.5351x; 2.5351x over previous
#include <cuda_runtime.h>
#include <cuda_bf16.h>
#include <math.h>

#define A_   128
#define D_   128
#define DM1  127
#define MAXB 64

// T probabilities (softmax rows of u_log_transition), bf16, 4 packed per uint2.
__device__ uint2  g_T[(size_t)DM1 * A_ * A_ / 4];
// Emission table: {sigmoid(l), sigmoid(-l)} = {p(x=1|a), p(x=0|a)} per (d,j).
__device__ float2 g_S2[D_ * A_];
// Initial-state probabilities (softmax of u_log_p_a1).
__device__ float  g_pa1[A_];

// ---------------------------------------------------------------------------
// Prep A: row softmax of u_log_transition -> g_T (bf16). One warp per row.
// ---------------------------------------------------------------------------
__global__ void k_prepT(const float* __restrict__ u) {
    int w = threadIdx.x >> 5, lane = threadIdx.x & 31;
    int row = blockIdx.x * 8 + w;
    if (row >= DM1 * A_) return;
    float4 v4 = reinterpret_cast<const float4*>(u)[(size_t)row * 32 + lane];
    float m = fmaxf(fmaxf(v4.x, v4.y), fmaxf(v4.z, v4.w));
    #pragma unroll
    for (int o = 16; o > 0; o >>= 1) m = fmaxf(m, __shfl_xor_sync(0xffffffffu, m, o));
    float e0 = __expf(v4.x - m), e1 = __expf(v4.y - m);
    float e2 = __expf(v4.z - m), e3 = __expf(v4.w - m);
    float s = e0 + e1 + e2 + e3;
    #pragma unroll
    for (int o = 16; o > 0; o >>= 1) s += __shfl_xor_sync(0xffffffffu, s, o);
    float inv = 1.0f / s;
    __nv_bfloat162 p0 = __floats2bfloat162_rn(e0 * inv, e1 * inv);
    __nv_bfloat162 p1 = __floats2bfloat162_rn(e2 * inv, e3 * inv);
    uint2 ov;
    ov.x = *reinterpret_cast<unsigned int*>(&p0);
    ov.y = *reinterpret_cast<unsigned int*>(&p1);
    g_T[(size_t)row * 32 + lane] = ov;
}

// ---------------------------------------------------------------------------
// Prep B: emission sigmoid table.
// ---------------------------------------------------------------------------
__global__ void k_prepS(const float* __restrict__ lpx) {
    int i = blockIdx.x * 256 + threadIdx.x;
    if (i < D_ * A_) {
        float l = lpx[i];
        float sp = 1.0f / (1.0f + __expf(-l));
        float sn = 1.0f / (1.0f + __expf(l));
        g_S2[i] = make_float2(sp, sn);
    }
}

// ---------------------------------------------------------------------------
// Prep C: softmax of u_log_p_a1 -> g_pa1 (probs); writes log_p_a1 output tail.
// ---------------------------------------------------------------------------
__global__ void k_pa1(const float* __restrict__ u, float* __restrict__ out,
                      int base, int out_size) {
    __shared__ float sred[4];
    int t = threadIdx.x, lane = t & 31, w = t >> 5;
    float v = u[t];
    float m = v;
    #pragma unroll
    for (int o = 16; o > 0; o >>= 1) m = fmaxf(m, __shfl_xor_sync(0xffffffffu, m, o));
    if (lane == 0) sred[w] = m;
    __syncthreads();
    m = fmaxf(fmaxf(sred[0], sred[1]), fmaxf(sred[2], sred[3]));
    __syncthreads();
    float e = __expf(v - m);
    float s = e;
    #pragma unroll
    for (int o = 16; o > 0; o >>= 1) s += __shfl_xor_sync(0xffffffffu, s, o);
    if (lane == 0) sred[w] = s;
    __syncthreads();
    s = sred[0] + sred[1] + sred[2] + sred[3];
    float lp = v - m - logf(s);
    g_pa1[t] = __expf(lp);
    int idx = base + t;
    if (idx < out_size) out[idx] = lp;
}

// ---------------------------------------------------------------------------
// Main forward recurrence. grid = B, block = 256 (8 warps).
// Warp w owns k/j slice [16w, 16w+16); lane l<16 of warp w holds v[16w+l] in
// a register. One barrier per step; T register-double-buffered; rescale
// every 8 steps computed redundantly by all threads.
// ---------------------------------------------------------------------------
__global__ void __launch_bounds__(256) k_forward(const float* __restrict__ x,
                                                 float* __restrict__ out,
                                                 int out_size) {
    const int b = blockIdx.x;
    const int t = threadIdx.x;
    const int w = t >> 5, lane = t & 31;
    const int kb = w * 16;

    __shared__ float part[2][8][A_];
    __shared__ float s_red[8];
    __shared__ float sx[D_];

    if (t < D_) sx[t] = x[b * D_ + t];
    __syncthreads();

    float v_reg = 0.f, acc = 0.f, e_pref = 0.f;
    if (lane < 16) {
        int j = kb + lane;
        float2 s0 = g_S2[j];
        float e0 = (sx[0] > 0.5f) ? s0.x : s0.y;
        v_reg = e0 * g_pa1[j];
        float2 s1 = g_S2[A_ + j];
        e_pref = (sx[1] > 0.5f) ? s1.x : s1.y;
    }

    uint2 TA[16], TB[16];
    {
        const uint2* tp = g_T + ((size_t)0 * A_ + kb) * 32 + lane;
        #pragma unroll
        for (int kk = 0; kk < 16; ++kk) TA[kk] = tp[kk * 32];
    }
    int buf = 0;

#define PREFETCH_T(DST, DMAT) do {                                          \
        const uint2* _tp = g_T + ((size_t)(DMAT) * A_ + kb) * 32 + lane;    \
        _Pragma("unroll")                                                   \
        for (int kk = 0; kk < 16; ++kk) (DST)[kk] = _tp[kk * 32];           \
    } while (0)

#define STEP(DD, TARR) do {                                                 \
        float ax = 0.f, ay = 0.f, az = 0.f, a4 = 0.f;                       \
        _Pragma("unroll")                                                   \
        for (int kk = 0; kk < 16; ++kk) {                                   \
            float vk = __shfl_sync(0xffffffffu, v_reg, kk);                 \
            float fx = __uint_as_float((TARR)[kk].x << 16);                 \
            float fy = __uint_as_float((TARR)[kk].x & 0xffff0000u);         \
            float fz = __uint_as_float((TARR)[kk].y << 16);                 \
            float fw = __uint_as_float((TARR)[kk].y & 0xffff0000u);         \
            ax = fmaf(vk, fx, ax); ay = fmaf(vk, fy, ay);                   \
            az = fmaf(vk, fz, az); a4 = fmaf(vk, fw, a4);                   \
        }                                                                   \
        *reinterpret_cast<float4*>(&part[buf][w][4 * lane]) =               \
            make_float4(ax, ay, az, a4);                                    \
        __syncthreads();                                                    \
        if (lane < 16) {                                                    \
            int j = kb + lane;                                              \
            float s = part[buf][0][j] + part[buf][1][j]                     \
                    + part[buf][2][j] + part[buf][3][j]                     \
                    + part[buf][4][j] + part[buf][5][j]                     \
                    + part[buf][6][j] + part[buf][7][j];                    \
            v_reg = s * e_pref;                                             \
            int dn = ((DD) + 1 < D_) ? (DD) + 1 : (DD);                     \
            float2 sn = g_S2[dn * A_ + j];                                  \
            e_pref = (sx[dn] > 0.5f) ? sn.x : sn.y;                         \
        }                                                                   \
        if (((DD) & 7) == 7) {                                              \
            float m = v_reg;                                                \
            m = fmaxf(m, __shfl_xor_sync(0xffffffffu, m, 8, 16));           \
            m = fmaxf(m, __shfl_xor_sync(0xffffffffu, m, 4, 16));           \
            m = fmaxf(m, __shfl_xor_sync(0xffffffffu, m, 2, 16));           \
            m = fmaxf(m, __shfl_xor_sync(0xffffffffu, m, 1, 16));           \
            if (lane == 0) s_red[w] = m;                                    \
            __syncthreads();                                                \
            float mm = fmaxf(                                               \
                fmaxf(fmaxf(s_red[0], s_red[1]), fmaxf(s_red[2], s_red[3])),\
                fmaxf(fmaxf(s_red[4], s_red[5]), fmaxf(s_red[6], s_red[7])));\
            float inv = 1.0f / mm;                                          \
            if (lane < 16) v_reg *= inv;                                    \
            acc += __logf(mm);                                              \
        }                                                                   \
        buf ^= 1;                                                           \
    } while (0)

    // steps d = 1 .. 126 in pairs, double-buffered T
    for (int i = 1; i < DM1; i += 2) {
        PREFETCH_T(TB, i);                       // T[i] used at step i+1
        STEP(i, TA);
        PREFETCH_T(TA, (i + 1 < DM1) ? (i + 1) : i); // T[i+1] used at step i+2
        STEP(i + 1, TB);
    }
    // final step d = 127 uses T[126] (in TA)
    STEP(DM1, TA);

#undef STEP
#undef PREFETCH_T

    // final: log_px[b] = acc + log(sum_j v[j])
    float sv = (lane < 16) ? v_reg : 0.f;
    sv += __shfl_xor_sync(0xffffffffu, sv, 8, 16);
    sv += __shfl_xor_sync(0xffffffffu, sv, 4, 16);
    sv += __shfl_xor_sync(0xffffffffu, sv, 2, 16);
    sv += __shfl_xor_sync(0xffffffffu, sv, 1, 16);
    if (lane == 0) s_red[w] = sv;
    __syncthreads();
    float tot = (s_red[0] + s_red[1]) + (s_red[2] + s_red[3])
              + (s_red[4] + s_red[5]) + (s_red[6] + s_red[7]);
    float res = acc + __logf(tot);
    if (t < A_) {
        int idx = b * A_ + t;
        if (idx < out_size) out[idx] = res;
    }
}

// ---------------------------------------------------------------------------
extern "C" void kernel_launch(void* const* d_in, const int* in_sizes, int n_in,
                              void* d_out, int out_size) {
    const float* x     = (const float*)d_in[0];   // [B, D]
    const float* u_pa1 = (const float*)d_in[1];   // [1,1,1,A]
    const float* u_T   = (const float*)d_in[2];   // [D-1, A, A]
    const float* lpx   = (const float*)d_in[3];   // [1, D, 1, A]
    float* out = (float*)d_out;

    int B = in_sizes[0] / D_;
    if (B > MAXB) B = MAXB;

    k_prepT<<<(DM1 * A_ + 7) / 8, 256>>>(u_T);
    k_prepS<<<(D_ * A_ + 255) / 256, 256>>>(lpx);
    k_pa1<<<1, 128>>>(u_pa1, out, B * A_, out_size);

    k_forward<<<B, 256>>>(x, out, out_size);
}